// round 11
// baseline (speedup 1.0000x reference)
#include <cuda_runtime.h>
#include <cuda_bf16.h>
#include <cuda_fp16.h>

// Problem constants (EdgeConv_33930241638504): N=50000, E=800000, IN=OUT=16, T=8
#define MAXN 50048
#define IN_F 16
#define OUT_F 16
#define T_F 8
#define LN_EPS 1e-5f
#define NB 128   // nodes per block in node_kernel

// Scratch (device globals: allocation-free rule)
// g fp16, 256B/node, layout [n][j=t/2][o][s=t&1]: half idx = n*128 + j*32 + o*2 + s.
__device__ __half g_gh[(size_t)MAXN * 128];   // 12.8 MB (L2-resident)
__device__ float  g_c[MAXN * OUT_F];          // c[n][o] fp32 (3.2 MB, L2-resident)
__device__ int    g_idx64;                    // 1 if edge_index int64, 0 if int32

__device__ __forceinline__ void mma16816(float* c, const unsigned* a, const unsigned* b)
{
    asm volatile("mma.sync.aligned.m16n8k16.row.col.f32.f16.f16.f32 "
                 "{%0,%1,%2,%3}, {%4,%5,%6,%7}, {%8,%9}, {%0,%1,%2,%3};"
                 : "+f"(c[0]), "+f"(c[1]), "+f"(c[2]), "+f"(c[3])
                 : "r"(a[0]), "r"(a[1]), "r"(a[2]), "r"(a[3]),
                   "r"(b[0]), "r"(b[1]));
}

// ---------------------------------------------------------------------------
// Kernel 1: node preprocessing on tensor cores.
// Per block: 128 nodes. LN (1 thread/node, register math) -> hs fp16 smem.
// Then per warp: one m16 node-tile, A = hs, B = W2[16 x 160] in smem
// (cols 0..127 = w_edge -> g, 128..143 = b_edge -> c, 144..159 = root -> out).
// 20x mma.m16n8k16. g staged permuted in smem -> coalesced uint4 copy.
// ---------------------------------------------------------------------------
__global__ __launch_bounds__(256) void node_kernel(
    const float* __restrict__ x,
    const float* __restrict__ ln_gamma,
    const float* __restrict__ ln_beta,
    const float* __restrict__ w_edge,   // [T, IN*OUT]
    const float* __restrict__ b_edge,   // [IN*OUT]
    const float* __restrict__ root,     // [IN, OUT]
    const float* __restrict__ bias,     // [OUT]
    const unsigned int* __restrict__ idx_raw,
    float* __restrict__ out,
    int N)
{
    __shared__ __half hs[NB][16];             // 4 KB  (row = 32B)
    __shared__ __half W2T[160 * 16];          // 5 KB  [col][k=i]
    __shared__ __half gstage[8][16 * 128];    // 32 KB (per-warp permuted g)
    __shared__ float  gbb[48];                // gamma | beta | bias

    // W2T fill: col<128 -> w_edge[t=col>>4][i*16 + (col&15)], then b_edge, root
    for (int idx = threadIdx.x; idx < 160 * 16; idx += 256) {
        int col = idx >> 4, i = idx & 15;
        float v;
        if (col < 128)      v = w_edge[(col >> 4) * 256 + i * 16 + (col & 15)];
        else if (col < 144) v = b_edge[i * 16 + (col - 128)];
        else                v = root[i * 16 + (col - 144)];
        W2T[col * 16 + i] = __float2half(v);
    }
    if (threadIdx.x < 16)      gbb[threadIdx.x] = ln_gamma[threadIdx.x];
    else if (threadIdx.x < 32) gbb[threadIdx.x] = ln_beta[threadIdx.x - 16];
    else if (threadIdx.x < 48) gbb[threadIdx.x] = bias[threadIdx.x - 32];

    // dtype detection (block 0, warp 0): int64 LE, values < N => odd words zero.
    if (blockIdx.x == 0 && threadIdx.x < 32) {
        int lane = threadIdx.x;
        unsigned int any = 0;
        #pragma unroll
        for (int k = 0; k < 8; k++) any |= idx_raw[2 * (lane * 8 + k) + 1];
        unsigned int ballot = __ballot_sync(0xffffffffu, any != 0);
        if (lane == 0) g_idx64 = (ballot == 0u) ? 1 : 0;
    }
    __syncthreads();   // gbb ready before LN uses it

    int nbase = blockIdx.x * NB;

    // LN: one thread per node, all in registers
    if (threadIdx.x < NB) {
        int node = nbase + threadIdx.x;
        int n = (node < N) ? node : (N - 1);
        const float4* xp = (const float4*)(x + (size_t)n * 16);
        float4 x0 = xp[0], x1 = xp[1], x2 = xp[2], x3 = xp[3];
        float xv[16] = {x0.x, x0.y, x0.z, x0.w, x1.x, x1.y, x1.z, x1.w,
                        x2.x, x2.y, x2.z, x2.w, x3.x, x3.y, x3.z, x3.w};
        float s = 0.f;
        #pragma unroll
        for (int i = 0; i < 16; i++) s += xv[i];
        float mu = s * (1.0f / 16.0f);
        float v = 0.f;
        #pragma unroll
        for (int i = 0; i < 16; i++) { float d = xv[i] - mu; v += d * d; }
        float rstd = rsqrtf(v * (1.0f / 16.0f) + LN_EPS);
        __half hh[16];
        #pragma unroll
        for (int i = 0; i < 16; i++) {
            float h = fmaxf((xv[i] - mu) * rstd * gbb[i] + gbb[16 + i], 0.f);
            hh[i] = __float2half(h);
        }
        const uint4* hp = (const uint4*)hh;
        *(uint4*)&hs[threadIdx.x][0] = hp[0];
        *(uint4*)&hs[threadIdx.x][8] = hp[1];
    }
    __syncthreads();

    int warp = threadIdx.x >> 5;
    int lane = threadIdx.x & 31;
    int grp  = lane >> 2;        // 0..7
    int tid  = lane & 3;         // 0..3

    // A fragment (16 nodes x 16 feats), standard m16n8k16 row-major layout
    unsigned a[4];
    a[0] = *(const unsigned*)&hs[warp * 16 + grp][tid * 2];
    a[1] = *(const unsigned*)&hs[warp * 16 + grp + 8][tid * 2];
    a[2] = *(const unsigned*)&hs[warp * 16 + grp][tid * 2 + 8];
    a[3] = *(const unsigned*)&hs[warp * 16 + grp + 8][tid * 2 + 8];

    __half* gst = &gstage[warp][0];
    int node0 = nbase + warp * 16 + grp;
    int node1 = node0 + 8;
    bool v0 = (node0 < N), v1 = (node1 < N);

    #pragma unroll
    for (int nt = 0; nt < 20; nt++) {
        int col0 = nt * 8 + grp;     // this thread's B column
        unsigned b[2];
        b[0] = *(const unsigned*)&W2T[col0 * 16 + tid * 2];
        b[1] = *(const unsigned*)&W2T[col0 * 16 + tid * 2 + 8];
        float c[4] = {0.f, 0.f, 0.f, 0.f};
        mma16816(c, a, b);
        // C: c0,c1 -> (row grp, cols nt*8 + 2tid, +1); c2,c3 -> row grp+8
        int o0 = (nt & 1) * 8 + tid * 2;   // o within 16 for this col pair
        if (nt < 16) {
            int t = nt >> 1, j = nt >> 2, sbit = t & 1;
            gst[grp * 128 + j * 32 + o0 * 2 + sbit]           = __float2half(c[0]);
            gst[grp * 128 + j * 32 + (o0 + 1) * 2 + sbit]     = __float2half(c[1]);
            gst[(grp + 8) * 128 + j * 32 + o0 * 2 + sbit]     = __float2half(c[2]);
            gst[(grp + 8) * 128 + j * 32 + (o0 + 1) * 2 + sbit] = __float2half(c[3]);
        } else if (nt < 18) {
            int oo = (nt - 16) * 8 + tid * 2;
            if (v0) *(float2*)&g_c[node0 * 16 + oo] = make_float2(c[0], c[1]);
            if (v1) *(float2*)&g_c[node1 * 16 + oo] = make_float2(c[2], c[3]);
        } else {
            int oo = (nt - 18) * 8 + tid * 2;
            float b0 = gbb[32 + oo], b1 = gbb[32 + oo + 1];
            if (v0) *(float2*)&out[node0 * 16 + oo] = make_float2(c[0] + b0, c[1] + b1);
            if (v1) *(float2*)&out[node1 * 16 + oo] = make_float2(c[2] + b0, c[3] + b1);
        }
    }
    __syncwarp();

    // coalesced copy: 16 nodes x 256B = 256 uint4 per warp
    const uint4* gsrc = (const uint4*)gst;
    uint4* gdst = (uint4*)(g_gh + (size_t)(nbase + warp * 16) * 128);
    #pragma unroll
    for (int kk = 0; kk < 8; kk++) {
        int u = kk * 32 + lane;
        int nd = nbase + warp * 16 + (u >> 4);
        if (nd < N) gdst[u] = gsrc[u];
    }
}

// ---------------------------------------------------------------------------
// Kernel 2: per-edge message + scatter (R8 version, 2 edges per quad-thread).
//   msg[o] = c[src,o] + sum_t ea[t]*g[src,t,o]
// ---------------------------------------------------------------------------
__global__ __launch_bounds__(256) void edge_kernel(
    const void* __restrict__ edge_index,       // [2, E] int64 OR int32
    const float* __restrict__ edge_attr,       // [E, 8]
    float* __restrict__ out,
    int E, int halfE)
{
    int tid = blockIdx.x * blockDim.x + threadIdx.x;
    int p = tid >> 2;
    int q = tid & 3;
    if (p >= halfE) return;

    int e0 = p;
    int e1 = p + halfE;
    bool has1 = (e1 < E);
    int e1c = has1 ? e1 : e0;

    int src0, dst0, src1, dst1;
    if (g_idx64) {
        const long long* ei = (const long long*)edge_index;
        src0 = (int)ei[e0];   dst0 = (int)ei[(long)E + e0];
        src1 = (int)ei[e1c];  dst1 = (int)ei[(long)E + e1c];
    } else {
        const int* ei = (const int*)edge_index;
        src0 = ei[e0];        dst0 = ei[E + e0];
        src1 = ei[e1c];       dst1 = ei[E + e1c];
    }

    const float4* eap = (const float4*)edge_attr;
    float4 a00 = eap[(long)e0 * 2];
    float4 a01 = eap[(long)e0 * 2 + 1];
    float4 a10 = eap[(long)e1c * 2];
    float4 a11 = eap[(long)e1c * 2 + 1];
    float ea0[T_F] = {a00.x, a00.y, a00.z, a00.w, a01.x, a01.y, a01.z, a01.w};
    float ea1[T_F] = {a10.x, a10.y, a10.z, a10.w, a11.x, a11.y, a11.z, a11.w};

    const float4* c4 = (const float4*)g_c;
    float4 m0 = c4[src0 * 4 + q];
    float4 m1 = c4[src1 * 4 + q];

    const uint4* g40 = (const uint4*)(g_gh + (size_t)src0 * 128);
    const uint4* g41 = (const uint4*)(g_gh + (size_t)src1 * 128);
    uint4 u0[4], u1[4];
    #pragma unroll
    for (int j = 0; j < 4; j++) { u0[j] = g40[j * 4 + q]; u1[j] = g41[j * 4 + q]; }

    #pragma unroll
    for (int j = 0; j < 4; j++) {
        float b0 = ea0[2 * j], b1 = ea0[2 * j + 1];
        float2 pp;
        pp = __half22float2(*(const __half2*)&u0[j].x);
        m0.x = fmaf(b0, pp.x, fmaf(b1, pp.y, m0.x));
        pp = __half22float2(*(const __half2*)&u0[j].y);
        m0.y = fmaf(b0, pp.x, fmaf(b1, pp.y, m0.y));
        pp = __half22float2(*(const __half2*)&u0[j].z);
        m0.z = fmaf(b0, pp.x, fmaf(b1, pp.y, m0.z));
        pp = __half22float2(*(const __half2*)&u0[j].w);
        m0.w = fmaf(b0, pp.x, fmaf(b1, pp.y, m0.w));

        float d0 = ea1[2 * j], d1 = ea1[2 * j + 1];
        pp = __half22float2(*(const __half2*)&u1[j].x);
        m1.x = fmaf(d0, pp.x, fmaf(d1, pp.y, m1.x));
        pp = __half22float2(*(const __half2*)&u1[j].y);
        m1.y = fmaf(d0, pp.x, fmaf(d1, pp.y, m1.y));
        pp = __half22float2(*(const __half2*)&u1[j].z);
        m1.z = fmaf(d0, pp.x, fmaf(d1, pp.y, m1.z));
        pp = __half22float2(*(const __half2*)&u1[j].w);
        m1.w = fmaf(d0, pp.x, fmaf(d1, pp.y, m1.w));
    }

    float* dp0 = out + (size_t)dst0 * OUT_F + q * 4;
    asm volatile("red.global.add.v4.f32 [%0], {%1, %2, %3, %4};"
                 :: "l"(dp0), "f"(m0.x), "f"(m0.y), "f"(m0.z), "f"(m0.w)
                 : "memory");
    if (has1) {
        float* dp1 = out + (size_t)dst1 * OUT_F + q * 4;
        asm volatile("red.global.add.v4.f32 [%0], {%1, %2, %3, %4};"
                     :: "l"(dp1), "f"(m1.x), "f"(m1.y), "f"(m1.z), "f"(m1.w)
                     : "memory");
    }
}

// ---------------------------------------------------------------------------
extern "C" void kernel_launch(void* const* d_in, const int* in_sizes, int n_in,
                              void* d_out, int out_size)
{
    const float* x        = (const float*)d_in[0];
    const void*  eidx     = d_in[1];
    const float* eattr    = (const float*)d_in[2];
    const float* ln_gamma = (const float*)d_in[3];
    const float* ln_beta  = (const float*)d_in[4];
    const float* w_edge   = (const float*)d_in[5];
    const float* b_edge   = (const float*)d_in[6];
    const float* root     = (const float*)d_in[7];
    const float* bias     = (const float*)d_in[8];
    float* out = (float*)d_out;

    int N = in_sizes[0] / IN_F;
    int E = in_sizes[1] / 2;
    int halfE = (E + 1) / 2;

    node_kernel<<<(N + NB - 1) / NB, 256>>>(x, ln_gamma, ln_beta, w_edge, b_edge,
                                            root, bias, (const unsigned int*)eidx,
                                            out, N);
    edge_kernel<<<(halfE * 4 + 255) / 256, 256>>>(eidx, eattr, out, E, halfE);
}